// round 15
// baseline (speedup 1.0000x reference)
#include <cuda_runtime.h>
#include <math.h>

#define NT 1024

// Fused TT-network:  y = log_softmax( x_pad @ W1_tt @ W2_tt )
// TT x TT (matching modes) = TT with cores G_k = contract_n(c1_k, c2_k).
// Zero-pad 177->3072 => only m1=m2=0 contribute; x zero-tail => m3>=6 dead.
//
// R15 vs R14 champion:
//  - G2 computes ONLY the 54 u-rows with m3<6 (rows m3 in {6,7} were never
//    read by A3) and reads c1_2/c2_2 DIRECTLY from global (L1-served) --
//    no SMEM staging at all, so G2 runs inside P0 concurrently with the
//    small-core warp groups.
//  - Chain: P0(G1/A1/A2 || G3/G4/G34i || G2) -> P1(V || A3) -> P2(logits).
//    Two barriers instead of four; SMEM ~26KB.
__global__ __launch_bounds__(NT) void tt_fused_kernel(
    const float* __restrict__ x,     // (64,177)
    const float* __restrict__ c1_0,  // (1,3,10,3)
    const float* __restrict__ c1_1,  // (3,4,20,3)
    const float* __restrict__ c1_2,  // (3,8,50,3)
    const float* __restrict__ c1_3,  // (3,4,20,3)
    const float* __restrict__ c1_4,  // (3,8,10,1)
    const float* __restrict__ c2_0,  // (1,10,1,3)
    const float* __restrict__ c2_1,  // (3,20,2,3)
    const float* __restrict__ c2_2,  // (3,50,5,3)
    const float* __restrict__ c2_3,  // (3,20,1,3)
    const float* __restrict__ c2_4,  // (3,10,1,1)
    float* __restrict__ out)         // (64,10)
{
    __shared__ float sG1[162];    // [r1(9), p2(2), r2(9)]  (m2=0)
    __shared__ float sG3[324];    // [r3, m4, r4]
    __shared__ float sG4[72];     // [r4, m5]
    __shared__ float sG34i[288];  // [idx(32)=m4*8+m5][r3(9)]
    __shared__ float sA1[9];
    __shared__ float sA2[18];     // [p2, r2]
    __shared__ float sG2[3240];   // [u(72)][v(45)]  (only m3<6 rows written)
    __shared__ float sV[1728];    // [bl(32)*54 + m3*9 + r3]
    __shared__ float sA3[540];    // [m3(6)*90 + c*9 + r3]

    const int tid = threadIdx.x;

    // ---------- x prefetch: 32 rows per block, 16 lanes per row ------------
    const int bl = tid >> 4, s5 = tid & 15;
    const int bg = bl + 32 * (int)blockIdx.x;
    float xv[12];
    if (tid < 512) {
        const float* xr = x + bg * 177;
        #pragma unroll
        for (int k = 0; k < 12; k++) {
            int j = s5 + 16 * k;
            xv[k] = (j < 177) ? __ldg(xr + j) : 0.f;
        }
    }

    // ---------- Phase 0: three concurrent warp groups ----------------------
    if (tid < 64) {
        // warps 0-1: G1_0 + A1 -> bar(1,64) -> A2
        for (int o = tid; o < 162; o += 64) {
            int r2 = o % 9, p2 = (o / 9) % 2, r1 = o / 18;
            int a1 = r1 / 3, b1 = r1 % 3, a2 = r2 / 3, b2 = r2 % 3;
            const float* pa = c1_1 + a1 * 240 + a2;          // m2=0, n-stride 3
            const float* pb = c2_1 + b1 * 120 + p2 * 3 + b2; // n-stride 6
            float acc = 0.f;
            #pragma unroll
            for (int n = 0; n < 20; n++) acc += pa[n * 3] * pb[n * 6];
            sG1[(r1 * 2 + p2) * 9 + r2] = acc;
        }
        if (tid < 9) {
            int a1 = tid / 3, b1 = tid % 3;
            float acc = 0.f;
            #pragma unroll
            for (int n = 0; n < 10; n++) acc += c1_0[n * 3 + a1] * c2_0[n * 3 + b1];
            sA1[tid] = acc;
        }
        asm volatile("bar.sync 1, 64;" ::: "memory");
        if (tid < 18) {
            int r2 = tid % 9, p2 = tid / 9;
            float acc = 0.f;
            #pragma unroll
            for (int r1 = 0; r1 < 9; r1++)
                acc += sA1[r1] * sG1[(r1 * 2 + p2) * 9 + r2];
            sA2[p2 * 9 + r2] = acc;
        }
    } else if (tid < 384) {
        // warps 2-11 (320 threads): G3, G4 -> bar(2,320) -> G34i
        int o2 = tid - 64;
        for (int o = o2; o < 324; o += 320) {
            int r4 = o % 9; int rest = o / 9;
            int m4 = rest % 4; int r3 = rest / 4;
            int a3 = r3 / 3, b3 = r3 % 3, a4 = r4 / 3, b4 = r4 % 3;
            const float* pa = c1_3 + (a3 * 4 + m4) * 60 + a4;  // n-stride 3
            const float* pb = c2_3 + b3 * 60 + b4;             // n-stride 3
            float acc = 0.f;
            #pragma unroll
            for (int n = 0; n < 20; n++) acc += pa[n * 3] * pb[n * 3];
            sG3[o] = acc;
        }
        if (o2 < 72) {
            int m5 = o2 % 8, r4 = o2 / 8;
            int a4 = r4 / 3, b4 = r4 % 3;
            const float* pa = c1_4 + (a4 * 8 + m5) * 10;
            const float* pb = c2_4 + b4 * 10;
            float acc = 0.f;
            #pragma unroll
            for (int n = 0; n < 10; n++) acc += pa[n] * pb[n];
            sG4[r4 * 8 + m5] = acc;
        }
        asm volatile("bar.sync 2, 320;" ::: "memory");
        if (o2 < 288) {
            int r3 = o2 / 32, idx = o2 % 32;
            int m4 = idx / 8, m5 = idx % 8;
            float acc = 0.f;
            #pragma unroll
            for (int r4 = 0; r4 < 9; r4++)
                acc += sG3[(r3 * 4 + m4) * 9 + r4] * sG4[r4 * 8 + m5];
            sG34i[idx * 9 + r3] = acc;
        }
    } else if (tid < 546) {
        // 162 threads: G2 live rows only (m3<6), 3x5 tiles, straight __ldg.
        // u' in [0,54): a2 = u'/18, rem = u'%18 = m3*3+a3, u = a2*24+rem.
        // Tiles of 3 rows never cross a2 (18 % 3 == 0).
        int t = tid - 384;
        int ut = t / 9, v0 = (t % 9) * 5;
        int up0 = ut * 3;
        int a2 = up0 / 18, rem0 = up0 % 18;
        int abase[3];
        #pragma unroll
        for (int i = 0; i < 3; i++) {
            int rr = rem0 + i;                       // m3*3 + a3
            abase[i] = a2 * 1200 + (rr / 3) * 150 + (rr % 3);
        }
        int bb = (v0 / 15) * 750 + (v0 % 15);        // b2*750 + p3*3+b3
        float acc[3][5] = {};
        #pragma unroll 5
        for (int k = 0; k < 50; k++) {
            float a[3], b[5];
            #pragma unroll
            for (int i = 0; i < 3; i++) a[i] = __ldg(c1_2 + abase[i] + k * 3);
            #pragma unroll
            for (int j = 0; j < 5; j++) b[j] = __ldg(c2_2 + bb + k * 15 + j);
            #pragma unroll
            for (int i = 0; i < 3; i++)
                #pragma unroll
                for (int j = 0; j < 5; j++) acc[i][j] = fmaf(a[i], b[j], acc[i][j]);
        }
        #pragma unroll
        for (int i = 0; i < 3; i++)
            #pragma unroll
            for (int j = 0; j < 5; j++)
                sG2[(a2 * 24 + rem0 + i) * 45 + (v0 + j)] = acc[i][j];
    }
    __syncthreads();

    // ---------- Phase 1: V (tid<512) || A3 (tid>=512) ----------------------
    if (tid < 512) {
        // V[bl,m3,r3] = sum_idx x[bl,32*m3+idx] * G34i[idx][r3], m3<6.
        float ga[9], gb[9];
        #pragma unroll
        for (int r3 = 0; r3 < 9; r3++) {
            ga[r3] = sG34i[s5 * 9 + r3];
            gb[r3] = sG34i[(16 + s5) * 9 + r3];
        }
        #pragma unroll
        for (int m3 = 0; m3 < 6; m3++) {
            float xa = xv[2 * m3], xb = xv[2 * m3 + 1];
            float part[9];
            #pragma unroll
            for (int r3 = 0; r3 < 9; r3++)
                part[r3] = fmaf(xa, ga[r3], xb * gb[r3]);
            #pragma unroll
            for (int off = 8; off > 0; off >>= 1)
                #pragma unroll
                for (int r3 = 0; r3 < 9; r3++)
                    part[r3] += __shfl_down_sync(0xffffffffu, part[r3], off, 16);
            if (s5 == 0) {
                #pragma unroll
                for (int r3 = 0; r3 < 9; r3++)
                    sV[bl * 54 + m3 * 9 + r3] = part[r3];
            }
        }
    } else {
        // A3[m3<6, c, r3] = sum_{a2,b2} A2[p2,(a2,b2)] * G2  (540 items)
        for (int o = tid - 512; o < 540; o += 512) {
            int m3 = o / 90; int c = (o % 90) / 9; int r3 = o % 9;
            int p2 = c / 5, p3 = c % 5;
            int a3 = r3 / 3, b3 = r3 % 3;
            float acc = 0.f;
            #pragma unroll
            for (int a2 = 0; a2 < 3; a2++)
                #pragma unroll
                for (int b2 = 0; b2 < 3; b2++)
                    acc += sA2[p2 * 9 + a2 * 3 + b2]
                         * sG2[(a2 * 24 + m3 * 3 + a3) * 45 + (b2 * 15 + p3 * 3 + b3)];
            sA3[o] = acc;
        }
    }
    __syncthreads();

    // ---------- Phase 2: logits[bg,c] = sum_{m3,r3} A3 * V + log_softmax ---
    if (tid < 512) {
        float acc[10];
        #pragma unroll
        for (int c = 0; c < 10; c++) acc[c] = 0.f;
        #pragma unroll
        for (int q = 0; q < 4; q++) {
            int p = s5 + 16 * q;
            if (p < 54) {
                int m3 = p / 9, r3 = p % 9;
                float v = sV[bl * 54 + p];
                const float* ar = sA3 + m3 * 90 + r3;   // + c*9
                #pragma unroll
                for (int c = 0; c < 10; c++)
                    acc[c] = fmaf(v, ar[c * 9], acc[c]);
            }
        }
        #pragma unroll
        for (int off = 8; off > 0; off >>= 1)
            #pragma unroll
            for (int c = 0; c < 10; c++)
                acc[c] += __shfl_down_sync(0xffffffffu, acc[c], off, 16);
        if (s5 == 0) {
            float m = -INFINITY;
            #pragma unroll
            for (int c = 0; c < 10; c++) m = fmaxf(m, acc[c]);
            float sum = 0.f;
            #pragma unroll
            for (int c = 0; c < 10; c++) sum += __expf(acc[c] - m);
            float lse = m + __logf(sum);
            #pragma unroll
            for (int c = 0; c < 10; c++) out[bg * 10 + c] = acc[c] - lse;
        }
    }
}

extern "C" void kernel_launch(void* const* d_in, const int* in_sizes, int n_in,
                              void* d_out, int out_size) {
    const float* x    = (const float*)d_in[0];
    const float* c1_0 = (const float*)d_in[1];
    const float* c1_1 = (const float*)d_in[2];
    const float* c1_2 = (const float*)d_in[3];
    const float* c1_3 = (const float*)d_in[4];
    const float* c1_4 = (const float*)d_in[5];
    const float* c2_0 = (const float*)d_in[6];
    const float* c2_1 = (const float*)d_in[7];
    const float* c2_2 = (const float*)d_in[8];
    const float* c2_3 = (const float*)d_in[9];
    const float* c2_4 = (const float*)d_in[10];
    float* out = (float*)d_out;

    tt_fused_kernel<<<2, NT>>>(x, c1_0, c1_1, c1_2, c1_3, c1_4,
                               c2_0, c2_1, c2_2, c2_3, c2_4, out);
}

// round 16
// speedup vs baseline: 1.4167x; 1.4167x over previous
#include <cuda_runtime.h>
#include <math.h>

#define NT 1024

// Fused TT-network:  y = log_softmax( x_pad @ W1_tt @ W2_tt )
// TT x TT (matching modes) = TT with cores G_k = contract_n(c1_k, c2_k).
// Zero-pad 177->3072 => only m1=m2=0 contribute; x zero-tail => m3>=6 dead.
//
// R16 = R14 champion (13.2us) with ONE change: G2 computes only the 54
// live u-rows (m3<6; rows m3 in {6,7} were never read by A3), still from
// staged SMEM (R15 proved staging is the prefetch engine; direct-LDG G2
// serializes cold DRAM latency). 3x5 tiles, 162 threads, same range.
// Chain: P0(warp-grouped cores + float4 staging) -> P1(V || G2) -> P2(A3)
// -> P3(logits).
__global__ __launch_bounds__(NT) void tt_fused_kernel(
    const float* __restrict__ x,     // (64,177)
    const float* __restrict__ c1_0,  // (1,3,10,3)
    const float* __restrict__ c1_1,  // (3,4,20,3)
    const float* __restrict__ c1_2,  // (3,8,50,3)
    const float* __restrict__ c1_3,  // (3,4,20,3)
    const float* __restrict__ c1_4,  // (3,8,10,1)
    const float* __restrict__ c2_0,  // (1,10,1,3)
    const float* __restrict__ c2_1,  // (3,20,2,3)
    const float* __restrict__ c2_2,  // (3,50,5,3)
    const float* __restrict__ c2_3,  // (3,20,1,3)
    const float* __restrict__ c2_4,  // (3,10,1,1)
    float* __restrict__ out)         // (64,10)
{
    __shared__ float sG1[162];    // [r1(9), p2(2), r2(9)]  (m2=0)   P0 only
    __shared__ float sG3[324];    // [r3, m4, r4]                     P0 only
    __shared__ float sG4[72];     // [r4, m5]                         P0 only
    __shared__ float sG34i[288];  // [idx(32)=m4*8+m5][r3(9)]
    __shared__ float sA1[9];
    __shared__ float sA2[18];     // [p2, r2]
    __shared__ float sG2[3240];   // [u(72)][v(45)]  (only m3<6 rows written)
    __shared__ float sV[1728];    // [bl(32)*54 + m3*9 + r3]
    __shared__ alignas(16) float sBUF[5850]; // sC1[0,3600)+sC2[3600,5850); P2+: sA3[0,540)

    float* sC1 = sBUF;            // staged c1_2 (flat)
    float* sC2 = sBUF + 3600;     // staged c2_2 (flat)
    float* sA3 = sBUF;            // [m3(6)*90 + c*9 + r3]  (after P1)

    const int tid = threadIdx.x;

    // ---------- x prefetch: 32 rows per block, 16 lanes per row ------------
    const int bl = tid >> 4, s5 = tid & 15;
    const int bg = bl + 32 * (int)blockIdx.x;
    float xv[12];
    if (tid < 512) {
        const float* xr = x + bg * 177;
        #pragma unroll
        for (int k = 0; k < 12; k++) {
            int j = s5 + 16 * k;
            xv[k] = (j < 177) ? __ldg(xr + j) : 0.f;
        }
    }

    // ---------- Phase 0: warp-grouped small cores + float4 staging ---------
    if (tid < 64) {
        // warps 0-1: G1_0 + A1 -> bar(1,64) -> A2
        for (int o = tid; o < 162; o += 64) {
            int r2 = o % 9, p2 = (o / 9) % 2, r1 = o / 18;
            int a1 = r1 / 3, b1 = r1 % 3, a2 = r2 / 3, b2 = r2 % 3;
            const float* pa = c1_1 + a1 * 240 + a2;          // m2=0, n-stride 3
            const float* pb = c2_1 + b1 * 120 + p2 * 3 + b2; // n-stride 6
            float acc = 0.f;
            #pragma unroll
            for (int n = 0; n < 20; n++) acc += pa[n * 3] * pb[n * 6];
            sG1[(r1 * 2 + p2) * 9 + r2] = acc;
        }
        if (tid < 9) {
            int a1 = tid / 3, b1 = tid % 3;
            float acc = 0.f;
            #pragma unroll
            for (int n = 0; n < 10; n++) acc += c1_0[n * 3 + a1] * c2_0[n * 3 + b1];
            sA1[tid] = acc;
        }
        asm volatile("bar.sync 1, 64;" ::: "memory");
        if (tid < 18) {
            int r2 = tid % 9, p2 = tid / 9;
            float acc = 0.f;
            #pragma unroll
            for (int r1 = 0; r1 < 9; r1++)
                acc += sA1[r1] * sG1[(r1 * 2 + p2) * 9 + r2];
            sA2[p2 * 9 + r2] = acc;
        }
    } else if (tid < 384) {
        // warps 2-11 (320 threads): G3, G4 -> bar(2,320) -> G34i
        int o2 = tid - 64;
        for (int o = o2; o < 324; o += 320) {
            int r4 = o % 9; int rest = o / 9;
            int m4 = rest % 4; int r3 = rest / 4;
            int a3 = r3 / 3, b3 = r3 % 3, a4 = r4 / 3, b4 = r4 % 3;
            const float* pa = c1_3 + (a3 * 4 + m4) * 60 + a4;  // n-stride 3
            const float* pb = c2_3 + b3 * 60 + b4;             // n-stride 3
            float acc = 0.f;
            #pragma unroll
            for (int n = 0; n < 20; n++) acc += pa[n * 3] * pb[n * 3];
            sG3[o] = acc;
        }
        if (o2 < 72) {
            int m5 = o2 % 8, r4 = o2 / 8;
            int a4 = r4 / 3, b4 = r4 % 3;
            const float* pa = c1_4 + (a4 * 8 + m5) * 10;
            const float* pb = c2_4 + b4 * 10;
            float acc = 0.f;
            #pragma unroll
            for (int n = 0; n < 10; n++) acc += pa[n] * pb[n];
            sG4[r4 * 8 + m5] = acc;
        }
        asm volatile("bar.sync 2, 320;" ::: "memory");
        if (o2 < 288) {
            int r3 = o2 / 32, idx = o2 % 32;
            int m4 = idx / 8, m5 = idx % 8;
            float acc = 0.f;
            #pragma unroll
            for (int r4 = 0; r4 < 9; r4++)
                acc += sG3[(r3 * 4 + m4) * 9 + r4] * sG4[r4 * 8 + m5];
            sG34i[idx * 9 + r3] = acc;
        }
    } else {
        // warps 12-31 (640 threads): float4 staging of c1_2 + c2_2
        const float4* g1 = (const float4*)c1_2;
        float4* s1 = (float4*)sC1;
        for (int i = tid - 384; i < 900; i += 640) s1[i] = g1[i];
        const float4* g2 = (const float4*)c2_2;
        float4* s2 = (float4*)sC2;
        for (int i = tid - 384; i < 562; i += 640) s2[i] = g2[i];   // 2248 floats
        int r = tid - 384;
        if (r < 2) sC2[2248 + r] = c2_2[2248 + r];
    }
    __syncthreads();

    // ---------- Phase 1: V (tid<512) || G2 live rows (tid in [512,674)) ----
    if (tid < 512) {
        // V[bl,m3,r3] = sum_idx x[bl,32*m3+idx] * G34i[idx][r3], m3<6.
        float ga[9], gb[9];
        #pragma unroll
        for (int r3 = 0; r3 < 9; r3++) {
            ga[r3] = sG34i[s5 * 9 + r3];
            gb[r3] = sG34i[(16 + s5) * 9 + r3];
        }
        #pragma unroll
        for (int m3 = 0; m3 < 6; m3++) {
            float xa = xv[2 * m3], xb = xv[2 * m3 + 1];
            float part[9];
            #pragma unroll
            for (int r3 = 0; r3 < 9; r3++)
                part[r3] = fmaf(xa, ga[r3], xb * gb[r3]);
            #pragma unroll
            for (int off = 8; off > 0; off >>= 1)
                #pragma unroll
                for (int r3 = 0; r3 < 9; r3++)
                    part[r3] += __shfl_down_sync(0xffffffffu, part[r3], off, 16);
            if (s5 == 0) {
                #pragma unroll
                for (int r3 = 0; r3 < 9; r3++)
                    sV[bl * 54 + m3 * 9 + r3] = part[r3];
            }
        }
    } else if (tid < 674) {
        // G2 live rows only (m3<6): 18 u-tiles (3 rows) x 9 v-tiles (5 cols)
        // = 162 threads. u' in [0,54): a2 = u'/18, rem = u'%18 = m3*3+a3,
        // u = a2*24+rem. 3-row tiles never cross a2 (18 % 3 == 0).
        int t = tid - 512;
        int ut = t / 9, v0 = (t % 9) * 5;
        int up0 = ut * 3;
        int a2 = up0 / 18, rem0 = up0 % 18;
        int abase[3];
        #pragma unroll
        for (int i = 0; i < 3; i++) {
            int rr = rem0 + i;                       // m3*3 + a3
            abase[i] = a2 * 1200 + (rr / 3) * 150 + (rr % 3);
        }
        int bb = (v0 / 15) * 750 + (v0 % 15);        // b2*750 + p3*3+b3
        float acc[3][5] = {};
        #pragma unroll 5
        for (int k = 0; k < 50; k++) {
            float a[3], b[5];
            #pragma unroll
            for (int i = 0; i < 3; i++) a[i] = sC1[abase[i] + k * 3];
            #pragma unroll
            for (int j = 0; j < 5; j++) b[j] = sC2[bb + k * 15 + j];
            #pragma unroll
            for (int i = 0; i < 3; i++)
                #pragma unroll
                for (int j = 0; j < 5; j++) acc[i][j] = fmaf(a[i], b[j], acc[i][j]);
        }
        #pragma unroll
        for (int i = 0; i < 3; i++)
            #pragma unroll
            for (int j = 0; j < 5; j++)
                sG2[(a2 * 24 + rem0 + i) * 45 + (v0 + j)] = acc[i][j];
    }
    __syncthreads();

    // ---------- Phase 2: A3[m3<6, c, r3] = sum_{a2,b2} A2 * G2  (540) ------
    if (tid < 540) {
        int o = tid;
        int m3 = o / 90; int c = (o % 90) / 9; int r3 = o % 9;
        int p2 = c / 5, p3 = c % 5;
        int a3 = r3 / 3, b3 = r3 % 3;
        float acc = 0.f;
        #pragma unroll
        for (int a2 = 0; a2 < 3; a2++)
            #pragma unroll
            for (int b2 = 0; b2 < 3; b2++)
                acc += sA2[p2 * 9 + a2 * 3 + b2]
                     * sG2[(a2 * 24 + m3 * 3 + a3) * 45 + (b2 * 15 + p3 * 3 + b3)];
        sA3[o] = acc;   // aliases dead sC1
    }
    __syncthreads();

    // ---------- Phase 3: logits[bg,c] = sum_{m3,r3} A3 * V + log_softmax ---
    if (tid < 512) {
        float acc[10];
        #pragma unroll
        for (int c = 0; c < 10; c++) acc[c] = 0.f;
        #pragma unroll
        for (int q = 0; q < 4; q++) {
            int p = s5 + 16 * q;
            if (p < 54) {
                int m3 = p / 9, r3 = p % 9;
                float v = sV[bl * 54 + p];
                const float* ar = sA3 + m3 * 90 + r3;   // + c*9
                #pragma unroll
                for (int c = 0; c < 10; c++)
                    acc[c] = fmaf(v, ar[c * 9], acc[c]);
            }
        }
        #pragma unroll
        for (int off = 8; off > 0; off >>= 1)
            #pragma unroll
            for (int c = 0; c < 10; c++)
                acc[c] += __shfl_down_sync(0xffffffffu, acc[c], off, 16);
        if (s5 == 0) {
            float m = -INFINITY;
            #pragma unroll
            for (int c = 0; c < 10; c++) m = fmaxf(m, acc[c]);
            float sum = 0.f;
            #pragma unroll
            for (int c = 0; c < 10; c++) sum += __expf(acc[c] - m);
            float lse = m + __logf(sum);
            #pragma unroll
            for (int c = 0; c < 10; c++) out[bg * 10 + c] = acc[c] - lse;
        }
    }
}

extern "C" void kernel_launch(void* const* d_in, const int* in_sizes, int n_in,
                              void* d_out, int out_size) {
    const float* x    = (const float*)d_in[0];
    const float* c1_0 = (const float*)d_in[1];
    const float* c1_1 = (const float*)d_in[2];
    const float* c1_2 = (const float*)d_in[3];
    const float* c1_3 = (const float*)d_in[4];
    const float* c1_4 = (const float*)d_in[5];
    const float* c2_0 = (const float*)d_in[6];
    const float* c2_1 = (const float*)d_in[7];
    const float* c2_2 = (const float*)d_in[8];
    const float* c2_3 = (const float*)d_in[9];
    const float* c2_4 = (const float*)d_in[10];
    float* out = (float*)d_out;

    tt_fused_kernel<<<2, NT>>>(x, c1_0, c1_1, c1_2, c1_3, c1_4,
                               c2_0, c2_1, c2_2, c2_3, c2_4, out);
}